// round 14
// baseline (speedup 1.0000x reference)
#include <cuda_runtime.h>
#include <cuda_fp16.h>
#include <math.h>

// ZINBDecoder R14: both feature tables fp16 (prepass), HMUL2 products,
// f32x2 dot accumulation, SEL-free lane-permuted 8-edge fold.
//   - rows: 2 lines (u) + 2 lines (v) per edge (was 4+4 in fp32)
//   - fold: each lane visits edges in an order keyed to its own lane bits
//     (b4,b3,b2), so every fold level is x + shfl_xor(y,k) with no SELs.
//     Quad q (lanes 4q..4q+3) ends holding edge q's (sm, sd, sp).
// out = [mu | disp | pi], fp32.

typedef unsigned long long u64;

#define ITERS 4   // 8 edges/iter -> 32 edges per warp
#define U_MAX (10240 * 128)
#define V_MAX (2048 * 128)

__device__ __align__(16) __half g_uh[U_MAX];   // fp16 copy of ufeats
__device__ __align__(16) __half g_vh[V_MAX];   // fp16 copy of ifeats

__global__ void cvt_u_kernel(const float4* __restrict__ src, int n4) {
    const int i = blockIdx.x * blockDim.x + threadIdx.x;
    if (i < n4) {
        const float4 f = src[i];
        __half2* dst = reinterpret_cast<__half2*>(g_uh);
        dst[2 * i]     = __floats2half2_rn(f.x, f.y);
        dst[2 * i + 1] = __floats2half2_rn(f.z, f.w);
    }
}

__global__ void cvt_v_kernel(const float4* __restrict__ src, int n4) {
    const int i = blockIdx.x * blockDim.x + threadIdx.x;
    if (i < n4) {
        const float4 f = src[i];
        __half2* dst = reinterpret_cast<__half2*>(g_vh);
        dst[2 * i]     = __floats2half2_rn(f.x, f.y);
        dst[2 * i + 1] = __floats2half2_rn(f.z, f.w);
    }
}

__device__ __forceinline__ u64 fmul2(u64 a, u64 b) {
    u64 d;
    asm("mul.rn.f32x2 %0, %1, %2;" : "=l"(d) : "l"(a), "l"(b));
    return d;
}

__device__ __forceinline__ u64 ffma2(u64 a, u64 b, u64 c) {
    u64 d;
    asm("fma.rn.f32x2 %0, %1, %2, %3;" : "=l"(d) : "l"(a), "l"(b), "l"(c));
    return d;
}

__device__ __forceinline__ u64 pack2(float lo, float hi) {
    u64 d;
    asm("mov.b64 %0, {%1, %2};" : "=l"(d) : "f"(lo), "f"(hi));
    return d;
}

__device__ __forceinline__ float unpack_sum(u64 p) {
    unsigned int lo, hi;
    asm("mov.b64 {%0, %1}, %2;" : "=r"(lo), "=r"(hi) : "l"(p));
    return __uint_as_float(lo) + __uint_as_float(hi);
}

__device__ __forceinline__ float fast_sigmoid(float x) {
    return __fdividef(1.0f, 1.0f + __expf(-x));
}

// Per-lane partial of edge (s,g): elements 4*lane .. 4*lane+3.
__device__ __forceinline__ void edge_partial(
    int s, int g, int lane,
    const ulonglong2& wm, const ulonglong2& wd, const ulonglong2& wp,
    float p[3])
{
    const uint2 ua = *reinterpret_cast<const uint2*>(g_uh + (size_t)s * 128 + 4 * lane);
    const uint2 va = *reinterpret_cast<const uint2*>(g_vh + (size_t)g * 128 + 4 * lane);
    const __half2 h01h = __hmul2(*reinterpret_cast<const __half2*>(&ua.x),
                                 *reinterpret_cast<const __half2*>(&va.x));
    const __half2 h23h = __hmul2(*reinterpret_cast<const __half2*>(&ua.y),
                                 *reinterpret_cast<const __half2*>(&va.y));
    const float2 f01 = __half22float2(h01h);
    const float2 f23 = __half22float2(h23h);
    const u64 h0 = pack2(f01.x, f01.y);
    const u64 h1 = pack2(f23.x, f23.y);
    u64 t;
    t = fmul2(h0, wm.x); t = ffma2(h1, wm.y, t); p[0] = unpack_sum(t);
    t = fmul2(h0, wd.x); t = ffma2(h1, wd.y, t); p[1] = unpack_sum(t);
    t = fmul2(h0, wp.x); t = ffma2(h1, wp.y, t); p[2] = unpack_sum(t);
}

__global__ void __launch_bounds__(256, 5)
zinb_kernel(const float* __restrict__ ge_factor,
            const float* __restrict__ sz_factor,
            const float* __restrict__ W_mean,
            const float* __restrict__ b_mean,
            const float* __restrict__ W_disp,
            const float* __restrict__ b_disp,
            const float* __restrict__ W_pi,
            const float* __restrict__ b_pi,
            const int*   __restrict__ src_idx,
            const int*   __restrict__ dst_idx,
            float* __restrict__ out,
            int E)
{
    const int tid  = threadIdx.x;
    const int lane = tid & 31;

    // Weight slices in registers: elements 4*lane .. 4*lane+3 (12 regs).
    const ulonglong2 wm = reinterpret_cast<const ulonglong2*>(W_mean)[lane];
    const ulonglong2 wd = reinterpret_cast<const ulonglong2*>(W_disp)[lane];
    const ulonglong2 wp = reinterpret_cast<const ulonglong2*>(W_pi)[lane];

    // Lane-permutation constants for the SEL-free fold.
    const int jKeepBase = (lane & 16) ? 4 : 0;  // edge bit2 = lane bit4
    const int jSendBase = 4 - jKeepBase;
    const int b3 = (lane >> 3) & 1;             // edge bit1 key
    const int b2 = (lane >> 2) & 1;             // edge bit0 key

    const int gwarp = (blockIdx.x * blockDim.x + tid) >> 5;
    const int base0 = gwarp * (8 * ITERS);      // warp's contiguous 32 edges
    const int jl    = lane & 7;

    // Preload indices for the first 8-edge group.
    int e_pf = base0 + jl;
    int s_l  = src_idx[(e_pf < E) ? e_pf : (E - 1)];
    int g_l  = dst_idx[(e_pf < E) ? e_pf : (E - 1)];

#pragma unroll 1
    for (int it = 0; it < ITERS; ++it) {
        const int base = base0 + it * 8;
        if (base >= E) break;

        const int s_cur = s_l;
        const int g_cur = g_l;

        // Prefetch next group's indices.
        if (it + 1 < ITERS) {
            e_pf = base + 8 + jl;
            const int e_c = (e_pf < E) ? e_pf : (E - 1);
            s_l = src_idx[e_c];
            g_l = dst_idx[e_c];
        }

        float r[12];

        // 4 pair-iterations; each computes send-edge then keep-edge and
        // folds across xor16 with a bare add (no SEL).
#pragma unroll
        for (int m1 = 0; m1 < 2; ++m1) {
#pragma unroll
            for (int m0 = 0; m0 < 2; ++m0) {
                const int low = ((m1 ^ b3) << 1) | (m0 ^ b2);
                const int jS  = jSendBase + low;
                const int jK  = jKeepBase + low;

                const int sS = __shfl_sync(0xFFFFFFFFu, s_cur, jS);
                const int gS = __shfl_sync(0xFFFFFFFFu, g_cur, jS);
                const int sK = __shfl_sync(0xFFFFFFFFu, s_cur, jK);
                const int gK = __shfl_sync(0xFFFFFFFFu, g_cur, jK);

                float pS[3], pK[3];
                edge_partial(sS, gS, lane, wm, wd, wp, pS);
                edge_partial(sK, gK, lane, wm, wd, wp, pK);

                const int idx = (m1 * 2 + m0) * 3;
#pragma unroll
                for (int i = 0; i < 3; ++i)
                    r[idx + i] = pK[i] + __shfl_xor_sync(0xFFFFFFFFu, pS[i], 16);
            }
        }

        // xor8 fold: m1=0 slots are keepers (t1 = b3).
        float f6[6];
#pragma unroll
        for (int m0 = 0; m0 < 2; ++m0)
#pragma unroll
            for (int i = 0; i < 3; ++i)
                f6[m0 * 3 + i] = r[m0 * 3 + i] +
                    __shfl_xor_sync(0xFFFFFFFFu, r[(2 + m0) * 3 + i], 8);

        // xor4 fold: m0=0 slots are keepers (t0 = b2). Quad q owns edge q.
        float A[3];
#pragma unroll
        for (int i = 0; i < 3; ++i)
            A[i] = f6[i] + __shfl_xor_sync(0xFFFFFFFFu, f6[3 + i], 4);

        // Butterfly within each quad (xor 2, 1).
#pragma unroll
        for (int off = 2; off >= 1; off >>= 1) {
            A[0] += __shfl_xor_sync(0xFFFFFFFFu, A[0], off);
            A[1] += __shfl_xor_sync(0xFFFFFFFFu, A[1], off);
            A[2] += __shfl_xor_sync(0xFFFFFFFFu, A[2], off);
        }

        // Leaders (lanes 0,4,...,28) handle edge (lane>>2).
        const int o   = lane >> 2;
        const int s_o = __shfl_sync(0xFFFFFFFFu, s_cur, o);
        const int g_o = __shfl_sync(0xFFFFFFFFu, g_cur, o);

        if ((lane & 3) == 0) {
            const int e = base + o;
            if (e < E) {
                const float gef = ge_factor[g_o];
                const float szf = sz_factor[s_o];

                const float mu_sig = fast_sigmoid(A[0] + b_mean[0]);
                const float pi_v   = fast_sigmoid(A[2] + b_pi[0]);

                // stable softplus: max(x,0) + log(1 + exp(-|x|))
                const float x = gef * (A[1] + b_disp[0]);
                float disp = fmaxf(x, 0.0f) + __logf(1.0f + __expf(-fabsf(x)));
                disp = fminf(fmaxf(disp, 1e-4f), 1e4f);

                float mu = __expf(gef * mu_sig) - 1.0f;   // arg in [0,1]
                mu = fminf(fmaxf(mu, 1e-5f), 1e6f);
                mu *= szf;

                out[e]                 = mu;
                out[(size_t)E + e]     = disp;
                out[(size_t)2 * E + e] = pi_v;
            }
        }
    }
}

extern "C" void kernel_launch(void* const* d_in, const int* in_sizes, int n_in,
                              void* d_out, int out_size)
{
    const float* ufeats    = (const float*)d_in[0];
    const float* ifeats    = (const float*)d_in[1];
    const float* ge_factor = (const float*)d_in[2];
    const float* sz_factor = (const float*)d_in[3];
    const float* W_mean    = (const float*)d_in[4];
    const float* b_mean    = (const float*)d_in[5];
    const float* W_disp    = (const float*)d_in[6];
    const float* b_disp    = (const float*)d_in[7];
    const float* W_pi      = (const float*)d_in[8];
    const float* b_pi      = (const float*)d_in[9];
    const int*   src_idx   = (const int*)d_in[10];
    const int*   dst_idx   = (const int*)d_in[11];
    float* out = (float*)d_out;
    (void)n_in; (void)out_size;

    const int E  = in_sizes[10];
    const int nu4 = in_sizes[0] / 4;
    const int nv4 = in_sizes[1] / 4;

    // Prepass: both feature tables -> fp16 scratch (stream-ordered).
    cvt_u_kernel<<<(nu4 + 255) / 256, 256>>>((const float4*)ufeats, nu4);
    cvt_v_kernel<<<(nv4 + 255) / 256, 256>>>((const float4*)ifeats, nv4);

    // 32 edges per warp, 8 warps per block -> 256 edges per block.
    const int threads = 256;
    const int edges_per_block = 8 * 8 * ITERS;
    const int blocks = (E + edges_per_block - 1) / edges_per_block;

    zinb_kernel<<<blocks, threads>>>(
        ge_factor, sz_factor,
        W_mean, b_mean, W_disp, b_disp, W_pi, b_pi,
        src_idx, dst_idx, out, E);
}

// round 15
// speedup vs baseline: 1.1716x; 1.1716x over previous
#include <cuda_runtime.h>
#include <cuda_fp16.h>
#include <math.h>

// ZINBDecoder R15: R13's proven converged structure (progressive xor16
// pair fold with SELs, broadcast edge rows, prefetch, 5 blocks/SM), with
// BOTH feature tables fp16 (prepass scratch). Rows: 2+2 lines/edge.
// Products via HMUL2, dot accumulated in f32x2. out = [mu|disp|pi], fp32.

typedef unsigned long long u64;

#define ITERS 4   // 8 edges/iter -> 32 edges per warp
#define U_MAX (10240 * 128)
#define V_MAX (2048 * 128)

__device__ __align__(16) __half g_uh[U_MAX];   // fp16 copy of ufeats
__device__ __align__(16) __half g_vh[V_MAX];   // fp16 copy of ifeats

__global__ void cvt_u_kernel(const float4* __restrict__ src, int n4) {
    const int i = blockIdx.x * blockDim.x + threadIdx.x;
    if (i < n4) {
        const float4 f = src[i];
        __half2* dst = reinterpret_cast<__half2*>(g_uh);
        dst[2 * i]     = __floats2half2_rn(f.x, f.y);
        dst[2 * i + 1] = __floats2half2_rn(f.z, f.w);
    }
}

__global__ void cvt_v_kernel(const float4* __restrict__ src, int n4) {
    const int i = blockIdx.x * blockDim.x + threadIdx.x;
    if (i < n4) {
        const float4 f = src[i];
        __half2* dst = reinterpret_cast<__half2*>(g_vh);
        dst[2 * i]     = __floats2half2_rn(f.x, f.y);
        dst[2 * i + 1] = __floats2half2_rn(f.z, f.w);
    }
}

__device__ __forceinline__ u64 fmul2(u64 a, u64 b) {
    u64 d;
    asm("mul.rn.f32x2 %0, %1, %2;" : "=l"(d) : "l"(a), "l"(b));
    return d;
}

__device__ __forceinline__ u64 ffma2(u64 a, u64 b, u64 c) {
    u64 d;
    asm("fma.rn.f32x2 %0, %1, %2, %3;" : "=l"(d) : "l"(a), "l"(b), "l"(c));
    return d;
}

__device__ __forceinline__ u64 pack2(float lo, float hi) {
    u64 d;
    asm("mov.b64 %0, {%1, %2};" : "=l"(d) : "f"(lo), "f"(hi));
    return d;
}

__device__ __forceinline__ float unpack_sum(u64 p) {
    unsigned int lo, hi;
    asm("mov.b64 {%0, %1}, %2;" : "=r"(lo), "=r"(hi) : "l"(p));
    return __uint_as_float(lo) + __uint_as_float(hi);
}

__device__ __forceinline__ float fast_sigmoid(float x) {
    return __fdividef(1.0f, 1.0f + __expf(-x));
}

// Per-lane partial of edge (s,g): elements 4*lane..4*lane+3.
// CONVERGED: s,g are warp-uniform (broadcast before the call).
__device__ __forceinline__ void edge_partial(
    int s, int g, int lane,
    const ulonglong2& wm, const ulonglong2& wd, const ulonglong2& wp,
    float p[3])
{
    const uint2 ua = *reinterpret_cast<const uint2*>(g_uh + (size_t)s * 128 + 4 * lane);
    const uint2 va = *reinterpret_cast<const uint2*>(g_vh + (size_t)g * 128 + 4 * lane);
    const __half2 h01h = __hmul2(*reinterpret_cast<const __half2*>(&ua.x),
                                 *reinterpret_cast<const __half2*>(&va.x));
    const __half2 h23h = __hmul2(*reinterpret_cast<const __half2*>(&ua.y),
                                 *reinterpret_cast<const __half2*>(&va.y));
    const float2 f01 = __half22float2(h01h);
    const float2 f23 = __half22float2(h23h);
    const u64 h0 = pack2(f01.x, f01.y);
    const u64 h1 = pack2(f23.x, f23.y);
    u64 t;
    t = fmul2(h0, wm.x); t = ffma2(h1, wm.y, t); p[0] = unpack_sum(t);
    t = fmul2(h0, wd.x); t = ffma2(h1, wd.y, t); p[1] = unpack_sum(t);
    t = fmul2(h0, wp.x); t = ffma2(h1, wp.y, t); p[2] = unpack_sum(t);
}

__global__ void __launch_bounds__(256, 5)
zinb_kernel(const float* __restrict__ ge_factor,
            const float* __restrict__ sz_factor,
            const float* __restrict__ W_mean,
            const float* __restrict__ b_mean,
            const float* __restrict__ W_disp,
            const float* __restrict__ b_disp,
            const float* __restrict__ W_pi,
            const float* __restrict__ b_pi,
            const int*   __restrict__ src_idx,
            const int*   __restrict__ dst_idx,
            float* __restrict__ out,
            int E)
{
    const int tid  = threadIdx.x;
    const int lane = tid & 31;

    // Weight slices in registers: elements 4*lane..4*lane+3 (12 regs).
    const ulonglong2 wm = reinterpret_cast<const ulonglong2*>(W_mean)[lane];
    const ulonglong2 wd = reinterpret_cast<const ulonglong2*>(W_disp)[lane];
    const ulonglong2 wp = reinterpret_cast<const ulonglong2*>(W_pi)[lane];

    const int gwarp = (blockIdx.x * blockDim.x + tid) >> 5;
    const int base0 = gwarp * (8 * ITERS);   // warp's contiguous 32 edges
    const int jl    = lane & 7;

    // Preload indices for the first 8-edge group.
    int e_pf = base0 + jl;
    int s_l  = src_idx[(e_pf < E) ? e_pf : (E - 1)];
    int g_l  = dst_idx[(e_pf < E) ? e_pf : (E - 1)];

#pragma unroll 1
    for (int it = 0; it < ITERS; ++it) {
        const int base = base0 + it * 8;
        if (base >= E) break;

        const int s_cur = s_l;
        const int g_cur = g_l;

        // Prefetch next group's indices.
        if (it + 1 < ITERS) {
            e_pf = base + 8 + jl;
            const int e_c = (e_pf < E) ? e_pf : (E - 1);
            s_l = src_idx[e_c];
            g_l = dst_idx[e_c];
        }

        float f[12];

        // Progressive fold: edges (jp, jp+4) computed then xor16-folded.
        // jp is warp-uniform -> all loads converged on a single row.
#pragma unroll
        for (int jp = 0; jp < 4; ++jp) {
            const int sA = __shfl_sync(0xFFFFFFFFu, s_cur, jp);
            const int gA = __shfl_sync(0xFFFFFFFFu, g_cur, jp);
            float aA[3];
            edge_partial(sA, gA, lane, wm, wd, wp, aA);

            const int sB = __shfl_sync(0xFFFFFFFFu, s_cur, jp + 4);
            const int gB = __shfl_sync(0xFFFFFFFFu, g_cur, jp + 4);
            float aB[3];
            edge_partial(sB, gB, lane, wm, wd, wp, aB);

            // xor16 fold: lanes bit4=0 keep edge jp, bit4=1 keep jp+4.
#pragma unroll
            for (int i = 0; i < 3; ++i) {
                const bool  hi   = (lane & 16) != 0;
                const float send = hi ? aA[i] : aB[i];
                const float keep = hi ? aB[i] : aA[i];
                f[jp * 3 + i] = keep + __shfl_xor_sync(0xFFFFFFFFu, send, 16);
            }
        }

        // 12 -> 6 (xor 8): edge bit1 := lane bit3.
#pragma unroll
        for (int i = 0; i < 6; ++i) {
            const bool  hi   = (lane & 8) != 0;
            const float send = hi ? f[i]     : f[i + 6];
            const float keep = hi ? f[i + 6] : f[i];
            f[i] = keep + __shfl_xor_sync(0xFFFFFFFFu, send, 8);
        }
        // 6 -> 3 (xor 4): edge bit0 := lane bit2. Quad q owns edge q.
#pragma unroll
        for (int i = 0; i < 3; ++i) {
            const bool  hi   = (lane & 4) != 0;
            const float send = hi ? f[i]     : f[i + 3];
            const float keep = hi ? f[i + 3] : f[i];
            f[i] = keep + __shfl_xor_sync(0xFFFFFFFFu, send, 4);
        }
        // Butterfly within each quad (xor 2, 1).
#pragma unroll
        for (int off = 2; off >= 1; off >>= 1) {
            f[0] += __shfl_xor_sync(0xFFFFFFFFu, f[0], off);
            f[1] += __shfl_xor_sync(0xFFFFFFFFu, f[1], off);
            f[2] += __shfl_xor_sync(0xFFFFFFFFu, f[2], off);
        }

        // Leaders (lanes 0,4,...,28) handle edge (lane>>2).
        const int o   = lane >> 2;
        const int s_o = __shfl_sync(0xFFFFFFFFu, s_cur, o);
        const int g_o = __shfl_sync(0xFFFFFFFFu, g_cur, o);

        if ((lane & 3) == 0) {
            const int e = base + o;
            if (e < E) {
                const float gef = ge_factor[g_o];
                const float szf = sz_factor[s_o];

                const float mu_sig = fast_sigmoid(f[0] + b_mean[0]);
                const float pi_v   = fast_sigmoid(f[2] + b_pi[0]);

                // stable softplus: max(x,0) + log(1 + exp(-|x|))
                const float x = gef * (f[1] + b_disp[0]);
                float disp = fmaxf(x, 0.0f) + __logf(1.0f + __expf(-fabsf(x)));
                disp = fminf(fmaxf(disp, 1e-4f), 1e4f);

                float mu = __expf(gef * mu_sig) - 1.0f;   // arg in [0,1]
                mu = fminf(fmaxf(mu, 1e-5f), 1e6f);
                mu *= szf;

                out[e]                 = mu;
                out[(size_t)E + e]     = disp;
                out[(size_t)2 * E + e] = pi_v;
            }
        }
    }
}

extern "C" void kernel_launch(void* const* d_in, const int* in_sizes, int n_in,
                              void* d_out, int out_size)
{
    const float* ufeats    = (const float*)d_in[0];
    const float* ifeats    = (const float*)d_in[1];
    const float* ge_factor = (const float*)d_in[2];
    const float* sz_factor = (const float*)d_in[3];
    const float* W_mean    = (const float*)d_in[4];
    const float* b_mean    = (const float*)d_in[5];
    const float* W_disp    = (const float*)d_in[6];
    const float* b_disp    = (const float*)d_in[7];
    const float* W_pi      = (const float*)d_in[8];
    const float* b_pi      = (const float*)d_in[9];
    const int*   src_idx   = (const int*)d_in[10];
    const int*   dst_idx   = (const int*)d_in[11];
    float* out = (float*)d_out;
    (void)n_in; (void)out_size;

    const int E   = in_sizes[10];
    const int nu4 = in_sizes[0] / 4;
    const int nv4 = in_sizes[1] / 4;

    // Prepass: both feature tables -> fp16 scratch (stream-ordered).
    cvt_u_kernel<<<(nu4 + 255) / 256, 256>>>((const float4*)ufeats, nu4);
    cvt_v_kernel<<<(nv4 + 255) / 256, 256>>>((const float4*)ifeats, nv4);

    // 32 edges per warp, 8 warps per block -> 256 edges per block.
    const int threads = 256;
    const int edges_per_block = 8 * 8 * ITERS;
    const int blocks = (E + edges_per_block - 1) / edges_per_block;

    zinb_kernel<<<blocks, threads>>>(
        ge_factor, sz_factor,
        W_mean, b_mean, W_disp, b_disp, W_pi, b_pi,
        src_idx, dst_idx, out, E);
}

// round 16
// speedup vs baseline: 1.4261x; 1.2172x over previous
#include <cuda_runtime.h>
#include <cuda_fp16.h>
#include <math.h>

// ZINBDecoder R16: fp16 tables; TWO edges per LDG.128 (half-warp split:
// lanes 0-15 own edge p, lanes 16-31 own edge p+4 -> the xor16 fold level
// disappears). fp16 HFMA2 weight stage. Folds xor8/xor4 + butterfly as in
// R15 (proven). out = [mu | disp | pi], fp32.

typedef unsigned long long u64;

#define ITERS 4   // 8 edges/iter -> 32 edges per warp
#define U_MAX (10240 * 128)
#define V_MAX (2048 * 128)

__device__ __align__(16) __half g_uh[U_MAX];   // fp16 copy of ufeats
__device__ __align__(16) __half g_vh[V_MAX];   // fp16 copy of ifeats

// Single prepass: converts both tables (u first, then v).
__global__ void cvt_kernel(const float4* __restrict__ u, int nu4,
                           const float4* __restrict__ v, int nv4) {
    const int i = blockIdx.x * blockDim.x + threadIdx.x;
    if (i < nu4) {
        const float4 f = u[i];
        __half2* dst = reinterpret_cast<__half2*>(g_uh);
        dst[2 * i]     = __floats2half2_rn(f.x, f.y);
        dst[2 * i + 1] = __floats2half2_rn(f.z, f.w);
    } else if (i < nu4 + nv4) {
        const int j = i - nu4;
        const float4 f = v[j];
        __half2* dst = reinterpret_cast<__half2*>(g_vh);
        dst[2 * j]     = __floats2half2_rn(f.x, f.y);
        dst[2 * j + 1] = __floats2half2_rn(f.z, f.w);
    }
}

__device__ __forceinline__ __half2 as_h2(unsigned int x) {
    return *reinterpret_cast<const __half2*>(&x);
}

__device__ __forceinline__ float fast_sigmoid(float x) {
    return __fdividef(1.0f, 1.0f + __expf(-x));
}

__global__ void __launch_bounds__(256, 5)
zinb_kernel(const float* __restrict__ ge_factor,
            const float* __restrict__ sz_factor,
            const float* __restrict__ W_mean,
            const float* __restrict__ b_mean,
            const float* __restrict__ W_disp,
            const float* __restrict__ b_disp,
            const float* __restrict__ W_pi,
            const float* __restrict__ b_pi,
            const int*   __restrict__ src_idx,
            const int*   __restrict__ dst_idx,
            float* __restrict__ out,
            int E)
{
    const int tid  = threadIdx.x;
    const int lane = tid & 31;
    const int half = (lane >> 4) & 1;   // 0: edge p, 1: edge p+4
    const int sl   = lane & 15;         // slice within the edge's row

    // fp16 weight slices: elements 8*sl .. 8*sl+7 as 4 half2 each (12 regs).
    __half2 wmh[4], wdh[4], wph[4];
    {
        const float4* wm4 = reinterpret_cast<const float4*>(W_mean) + 2 * sl;
        const float4* wd4 = reinterpret_cast<const float4*>(W_disp) + 2 * sl;
        const float4* wp4 = reinterpret_cast<const float4*>(W_pi)   + 2 * sl;
#pragma unroll
        for (int q = 0; q < 2; ++q) {
            const float4 m = wm4[q], d = wd4[q], p = wp4[q];
            wmh[2*q]   = __floats2half2_rn(m.x, m.y);
            wmh[2*q+1] = __floats2half2_rn(m.z, m.w);
            wdh[2*q]   = __floats2half2_rn(d.x, d.y);
            wdh[2*q+1] = __floats2half2_rn(d.z, d.w);
            wph[2*q]   = __floats2half2_rn(p.x, p.y);
            wph[2*q+1] = __floats2half2_rn(p.z, p.w);
        }
    }

    const int gwarp = (blockIdx.x * blockDim.x + tid) >> 5;
    const int base0 = gwarp * (8 * ITERS);   // warp's contiguous 32 edges
    const int jl    = lane & 7;

    // Preload indices for the first 8-edge group.
    int e_pf = base0 + jl;
    int s_l  = src_idx[(e_pf < E) ? e_pf : (E - 1)];
    int g_l  = dst_idx[(e_pf < E) ? e_pf : (E - 1)];

#pragma unroll 1
    for (int it = 0; it < ITERS; ++it) {
        const int base = base0 + it * 8;
        if (base >= E) break;

        const int s_cur = s_l;
        const int g_cur = g_l;

        // Prefetch next group's indices.
        if (it + 1 < ITERS) {
            e_pf = base + 8 + jl;
            const int e_c = (e_pf < E) ? e_pf : (E - 1);
            s_l = src_idx[e_c];
            g_l = dst_idx[e_c];
        }

        float f[12];

        // 4 pair-iterations; each LDG.128 covers two edges (one per half-warp).
#pragma unroll
        for (int p = 0; p < 4; ++p) {
            // Per-lane source lane p (lo half) or p+4 (hi half): SHFL.IDX,
            // uniform within each half-warp -> loads converged per half.
            const int s = __shfl_sync(0xFFFFFFFFu, s_cur, p + 4 * half);
            const int g = __shfl_sync(0xFFFFFFFFu, g_cur, p + 4 * half);

            const uint4 ua = *reinterpret_cast<const uint4*>(
                g_uh + (size_t)s * 128 + 8 * sl);
            const uint4 va = *reinterpret_cast<const uint4*>(
                g_vh + (size_t)g * 128 + 8 * sl);

            const __half2 h0 = __hmul2(as_h2(ua.x), as_h2(va.x));
            const __half2 h1 = __hmul2(as_h2(ua.y), as_h2(va.y));
            const __half2 h2 = __hmul2(as_h2(ua.z), as_h2(va.z));
            const __half2 h3 = __hmul2(as_h2(ua.w), as_h2(va.w));

            __half2 am = __hmul2(h0, wmh[0]);
            am = __hfma2(h1, wmh[1], am);
            am = __hfma2(h2, wmh[2], am);
            am = __hfma2(h3, wmh[3], am);
            __half2 ad = __hmul2(h0, wdh[0]);
            ad = __hfma2(h1, wdh[1], ad);
            ad = __hfma2(h2, wdh[2], ad);
            ad = __hfma2(h3, wdh[3], ad);
            __half2 ap = __hmul2(h0, wph[0]);
            ap = __hfma2(h1, wph[1], ap);
            ap = __hfma2(h2, wph[2], ap);
            ap = __hfma2(h3, wph[3], ap);

            const float2 fm = __half22float2(am);
            const float2 fd = __half22float2(ad);
            const float2 fp = __half22float2(ap);
            f[p * 3 + 0] = fm.x + fm.y;   // partial of edge (p + 4*half)
            f[p * 3 + 1] = fd.x + fd.y;
            f[p * 3 + 2] = fp.x + fp.y;
        }

        // State matches R15 post-xor16: f[p] holds edge (p + 4*b4) partials.
        // 12 -> 6 (xor 8): edge bit1 := lane bit3.
#pragma unroll
        for (int i = 0; i < 6; ++i) {
            const bool  hi   = (lane & 8) != 0;
            const float send = hi ? f[i]     : f[i + 6];
            const float keep = hi ? f[i + 6] : f[i];
            f[i] = keep + __shfl_xor_sync(0xFFFFFFFFu, send, 8);
        }
        // 6 -> 3 (xor 4): edge bit0 := lane bit2. Quad q owns edge q.
#pragma unroll
        for (int i = 0; i < 3; ++i) {
            const bool  hi   = (lane & 4) != 0;
            const float send = hi ? f[i]     : f[i + 3];
            const float keep = hi ? f[i + 3] : f[i];
            f[i] = keep + __shfl_xor_sync(0xFFFFFFFFu, send, 4);
        }
        // Butterfly within each quad (xor 2, 1): sums remaining slices.
#pragma unroll
        for (int off = 2; off >= 1; off >>= 1) {
            f[0] += __shfl_xor_sync(0xFFFFFFFFu, f[0], off);
            f[1] += __shfl_xor_sync(0xFFFFFFFFu, f[1], off);
            f[2] += __shfl_xor_sync(0xFFFFFFFFu, f[2], off);
        }

        // Leaders (lanes 0,4,...,28) handle edge (lane>>2).
        const int o   = lane >> 2;
        const int s_o = __shfl_sync(0xFFFFFFFFu, s_cur, o);
        const int g_o = __shfl_sync(0xFFFFFFFFu, g_cur, o);

        if ((lane & 3) == 0) {
            const int e = base + o;
            if (e < E) {
                const float gef = ge_factor[g_o];
                const float szf = sz_factor[s_o];

                const float mu_sig = fast_sigmoid(f[0] + b_mean[0]);
                const float pi_v   = fast_sigmoid(f[2] + b_pi[0]);

                // stable softplus: max(x,0) + log(1 + exp(-|x|))
                const float x = gef * (f[1] + b_disp[0]);
                float disp = fmaxf(x, 0.0f) + __logf(1.0f + __expf(-fabsf(x)));
                disp = fminf(fmaxf(disp, 1e-4f), 1e4f);

                float mu = __expf(gef * mu_sig) - 1.0f;   // arg in [0,1]
                mu = fminf(fmaxf(mu, 1e-5f), 1e6f);
                mu *= szf;

                out[e]                 = mu;
                out[(size_t)E + e]     = disp;
                out[(size_t)2 * E + e] = pi_v;
            }
        }
    }
}

extern "C" void kernel_launch(void* const* d_in, const int* in_sizes, int n_in,
                              void* d_out, int out_size)
{
    const float* ufeats    = (const float*)d_in[0];
    const float* ifeats    = (const float*)d_in[1];
    const float* ge_factor = (const float*)d_in[2];
    const float* sz_factor = (const float*)d_in[3];
    const float* W_mean    = (const float*)d_in[4];
    const float* b_mean    = (const float*)d_in[5];
    const float* W_disp    = (const float*)d_in[6];
    const float* b_disp    = (const float*)d_in[7];
    const float* W_pi      = (const float*)d_in[8];
    const float* b_pi      = (const float*)d_in[9];
    const int*   src_idx   = (const int*)d_in[10];
    const int*   dst_idx   = (const int*)d_in[11];
    float* out = (float*)d_out;
    (void)n_in; (void)out_size;

    const int E   = in_sizes[10];
    const int nu4 = in_sizes[0] / 4;
    const int nv4 = in_sizes[1] / 4;

    // Single prepass kernel converts both tables.
    cvt_kernel<<<(nu4 + nv4 + 255) / 256, 256>>>(
        (const float4*)ufeats, nu4, (const float4*)ifeats, nv4);

    // 32 edges per warp, 8 warps per block -> 256 edges per block.
    const int threads = 256;
    const int edges_per_block = 8 * 8 * ITERS;
    const int blocks = (E + edges_per_block - 1) / edges_per_block;

    zinb_kernel<<<blocks, threads>>>(
        ge_factor, sz_factor,
        W_mean, b_mean, W_disp, b_disp, W_pi, b_pi,
        src_idx, dst_idx, out, E);
}

// round 17
// speedup vs baseline: 1.4496x; 1.0165x over previous
#include <cuda_runtime.h>
#include <cuda_fp16.h>
#include <math.h>

// ZINBDecoder R17: fp16 tables; 2 edges/LDG.128 (half-warp) + b3-permuted
// edge assignment so the xor8 fold is SEL-free (bare add+shfl). Each LDG
// covers 4 edges x 1 full 128B line (granularity preserved). ITERS=8 for
// weight amortization. Folds xor4 + butterfly as in R16 (proven).
// out = [mu | disp | pi], fp32.

typedef unsigned long long u64;

#define ITERS 8   // 8 edges/iter -> 64 edges per warp
#define U_MAX (10240 * 128)
#define V_MAX (2048 * 128)

__device__ __align__(16) __half g_uh[U_MAX];   // fp16 copy of ufeats
__device__ __align__(16) __half g_vh[V_MAX];   // fp16 copy of ifeats

// Single prepass: converts both tables; one 8B store per thread.
__global__ void cvt_kernel(const float4* __restrict__ u, int nu4,
                           const float4* __restrict__ v, int nv4) {
    const int i = blockIdx.x * blockDim.x + threadIdx.x;
    if (i < nu4) {
        const float4 f = u[i];
        uint2 o;
        *reinterpret_cast<__half2*>(&o.x) = __floats2half2_rn(f.x, f.y);
        *reinterpret_cast<__half2*>(&o.y) = __floats2half2_rn(f.z, f.w);
        *reinterpret_cast<uint2*>(g_uh + 4 * (size_t)i) = o;
    } else if (i < nu4 + nv4) {
        const int j = i - nu4;
        const float4 f = v[j];
        uint2 o;
        *reinterpret_cast<__half2*>(&o.x) = __floats2half2_rn(f.x, f.y);
        *reinterpret_cast<__half2*>(&o.y) = __floats2half2_rn(f.z, f.w);
        *reinterpret_cast<uint2*>(g_vh + 4 * (size_t)j) = o;
    }
}

__device__ __forceinline__ __half2 as_h2(unsigned int x) {
    return *reinterpret_cast<const __half2*>(&x);
}

__device__ __forceinline__ float fast_sigmoid(float x) {
    return __fdividef(1.0f, 1.0f + __expf(-x));
}

__global__ void __launch_bounds__(256, 5)
zinb_kernel(const float* __restrict__ ge_factor,
            const float* __restrict__ sz_factor,
            const float* __restrict__ W_mean,
            const float* __restrict__ b_mean,
            const float* __restrict__ W_disp,
            const float* __restrict__ b_disp,
            const float* __restrict__ W_pi,
            const float* __restrict__ b_pi,
            const int*   __restrict__ src_idx,
            const int*   __restrict__ dst_idx,
            float* __restrict__ out,
            int E)
{
    const int tid  = threadIdx.x;
    const int lane = tid & 31;
    const int half = (lane >> 4) & 1;   // edge bit2
    const int b3   = (lane >> 3) & 1;   // edge-permute key for SEL-free xor8
    const int sl   = lane & 15;         // 16B slice within the edge's row

    // Edge-index bases: iteration (m1,m0) -> edge (m1?jb1:jb0)+m0.
    const int jb0 = 4 * half + 2 * b3;        // m1 = 0
    const int jb1 = 4 * half + 2 * (1 - b3);  // m1 = 1

    // fp16 weight slices: elements 8*sl .. 8*sl+7 as 4 half2 each (12 regs).
    __half2 wmh[4], wdh[4], wph[4];
    {
        const float4* wm4 = reinterpret_cast<const float4*>(W_mean) + 2 * sl;
        const float4* wd4 = reinterpret_cast<const float4*>(W_disp) + 2 * sl;
        const float4* wp4 = reinterpret_cast<const float4*>(W_pi)   + 2 * sl;
#pragma unroll
        for (int q = 0; q < 2; ++q) {
            const float4 m = wm4[q], d = wd4[q], p = wp4[q];
            wmh[2*q]   = __floats2half2_rn(m.x, m.y);
            wmh[2*q+1] = __floats2half2_rn(m.z, m.w);
            wdh[2*q]   = __floats2half2_rn(d.x, d.y);
            wdh[2*q+1] = __floats2half2_rn(d.z, d.w);
            wph[2*q]   = __floats2half2_rn(p.x, p.y);
            wph[2*q+1] = __floats2half2_rn(p.z, p.w);
        }
    }

    const int gwarp = (blockIdx.x * blockDim.x + tid) >> 5;
    const int base0 = gwarp * (8 * ITERS);   // warp's contiguous 64 edges
    const int jl    = lane & 7;

    // Preload indices for the first 8-edge group.
    int e_pf = base0 + jl;
    int s_l  = src_idx[(e_pf < E) ? e_pf : (E - 1)];
    int g_l  = dst_idx[(e_pf < E) ? e_pf : (E - 1)];

#pragma unroll 1
    for (int it = 0; it < ITERS; ++it) {
        const int base = base0 + it * 8;
        if (base >= E) break;

        const int s_cur = s_l;
        const int g_cur = g_l;

        // Prefetch next group's indices.
        if (it + 1 < ITERS) {
            e_pf = base + 8 + jl;
            const int e_c = (e_pf < E) ? e_pf : (E - 1);
            s_l = src_idx[e_c];
            g_l = dst_idx[e_c];
        }

        float f[12];

        // 4 iterations (m1,m0); lane handles edge (m1?jb1:jb0)+m0 and its
        // own 16B slice. Each LDG.128: 4 edges x 1 full 128B line each.
#pragma unroll
        for (int m1 = 0; m1 < 2; ++m1) {
#pragma unroll
            for (int m0 = 0; m0 < 2; ++m0) {
                const int j = (m1 ? jb1 : jb0) + m0;
                const int s = __shfl_sync(0xFFFFFFFFu, s_cur, j);
                const int g = __shfl_sync(0xFFFFFFFFu, g_cur, j);

                const uint4 ua = *reinterpret_cast<const uint4*>(
                    g_uh + (size_t)s * 128 + 8 * sl);
                const uint4 va = *reinterpret_cast<const uint4*>(
                    g_vh + (size_t)g * 128 + 8 * sl);

                const __half2 h0 = __hmul2(as_h2(ua.x), as_h2(va.x));
                const __half2 h1 = __hmul2(as_h2(ua.y), as_h2(va.y));
                const __half2 h2 = __hmul2(as_h2(ua.z), as_h2(va.z));
                const __half2 h3 = __hmul2(as_h2(ua.w), as_h2(va.w));

                __half2 am = __hmul2(h0, wmh[0]);
                am = __hfma2(h1, wmh[1], am);
                am = __hfma2(h2, wmh[2], am);
                am = __hfma2(h3, wmh[3], am);
                __half2 ad = __hmul2(h0, wdh[0]);
                ad = __hfma2(h1, wdh[1], ad);
                ad = __hfma2(h2, wdh[2], ad);
                ad = __hfma2(h3, wdh[3], ad);
                __half2 ap = __hmul2(h0, wph[0]);
                ap = __hfma2(h1, wph[1], ap);
                ap = __hfma2(h2, wph[2], ap);
                ap = __hfma2(h3, wph[3], ap);

                const float2 fm = __half22float2(am);
                const float2 fd = __half22float2(ad);
                const float2 fp = __half22float2(ap);
                const int idx = (m1 * 2 + m0) * 3;
                f[idx + 0] = fm.x + fm.y;
                f[idx + 1] = fd.x + fd.y;
                f[idx + 2] = fp.x + fp.y;
            }
        }

        // SEL-free xor8 fold: partner (lane^8) holds the SAME edge's other
        // row half in slot m1=1 (since 1 xor !b3 == b3). Bare add+shfl.
        // Result: f[m0*3+i] holds edge (4*half + 2*b3 + m0) == R16 layout.
#pragma unroll
        for (int i = 0; i < 6; ++i)
            f[i] += __shfl_xor_sync(0xFFFFFFFFu, f[i + 6], 8);

        // 6 -> 3 (xor 4): edge bit0 := lane bit2. Quad q owns edge q.
#pragma unroll
        for (int i = 0; i < 3; ++i) {
            const bool  hi   = (lane & 4) != 0;
            const float send = hi ? f[i]     : f[i + 3];
            const float keep = hi ? f[i + 3] : f[i];
            f[i] = keep + __shfl_xor_sync(0xFFFFFFFFu, send, 4);
        }
        // Butterfly within each quad (xor 2, 1): sums remaining slices.
#pragma unroll
        for (int off = 2; off >= 1; off >>= 1) {
            f[0] += __shfl_xor_sync(0xFFFFFFFFu, f[0], off);
            f[1] += __shfl_xor_sync(0xFFFFFFFFu, f[1], off);
            f[2] += __shfl_xor_sync(0xFFFFFFFFu, f[2], off);
        }

        // Leaders (lanes 0,4,...,28) handle edge (lane>>2).
        const int o   = lane >> 2;
        const int s_o = __shfl_sync(0xFFFFFFFFu, s_cur, o);
        const int g_o = __shfl_sync(0xFFFFFFFFu, g_cur, o);

        if ((lane & 3) == 0) {
            const int e = base + o;
            if (e < E) {
                const float gef = ge_factor[g_o];
                const float szf = sz_factor[s_o];

                const float mu_sig = fast_sigmoid(f[0] + b_mean[0]);
                const float pi_v   = fast_sigmoid(f[2] + b_pi[0]);

                // stable softplus: max(x,0) + log(1 + exp(-|x|))
                const float x = gef * (f[1] + b_disp[0]);
                float disp = fmaxf(x, 0.0f) + __logf(1.0f + __expf(-fabsf(x)));
                disp = fminf(fmaxf(disp, 1e-4f), 1e4f);

                float mu = __expf(gef * mu_sig) - 1.0f;   // arg in [0,1]
                mu = fminf(fmaxf(mu, 1e-5f), 1e6f);
                mu *= szf;

                out[e]                 = mu;
                out[(size_t)E + e]     = disp;
                out[(size_t)2 * E + e] = pi_v;
            }
        }
    }
}

extern "C" void kernel_launch(void* const* d_in, const int* in_sizes, int n_in,
                              void* d_out, int out_size)
{
    const float* ufeats    = (const float*)d_in[0];
    const float* ifeats    = (const float*)d_in[1];
    const float* ge_factor = (const float*)d_in[2];
    const float* sz_factor = (const float*)d_in[3];
    const float* W_mean    = (const float*)d_in[4];
    const float* b_mean    = (const float*)d_in[5];
    const float* W_disp    = (const float*)d_in[6];
    const float* b_disp    = (const float*)d_in[7];
    const float* W_pi      = (const float*)d_in[8];
    const float* b_pi      = (const float*)d_in[9];
    const int*   src_idx   = (const int*)d_in[10];
    const int*   dst_idx   = (const int*)d_in[11];
    float* out = (float*)d_out;
    (void)n_in; (void)out_size;

    const int E   = in_sizes[10];
    const int nu4 = in_sizes[0] / 4;
    const int nv4 = in_sizes[1] / 4;

    // Single prepass kernel converts both tables.
    cvt_kernel<<<(nu4 + nv4 + 255) / 256, 256>>>(
        (const float4*)ufeats, nu4, (const float4*)ifeats, nv4);

    // 64 edges per warp, 8 warps per block -> 512 edges per block.
    const int threads = 256;
    const int edges_per_block = 8 * 8 * ITERS;
    const int blocks = (E + edges_per_block - 1) / edges_per_block;

    zinb_kernel<<<blocks, threads>>>(
        ge_factor, sz_factor,
        W_mean, b_mean, W_disp, b_disp, W_pi, b_pi,
        src_idx, dst_idx, out, E);
}